// round 5
// baseline (speedup 1.0000x reference)
#include <cuda_runtime.h>
#include <math.h>

#define F_IN 128
#define HID  16
#define NC   10
#define CP   12
#define N_MAX 100000
#define E_MAX 1600000
#define SCAN_BLK 1024

// ---------------- scratch (allocation-free, 16B-aligned) ----------------
__device__ __align__(16) float g_aq   [N_MAX * 32];   // per node: a0[16] | ad[16]  (one 128B line)
__device__ __align__(16) float g_base1[N_MAX * HID];  // x @ root1 + b1
__device__ __align__(16) float g_h    [N_MAX * HID];  // ELU(layer1 out)
__device__ __align__(16) float g_bq   [N_MAX * 32];   // per node: b0[12] | bd[12] | pad[8]
__device__ __align__(16) float g_base2[N_MAX * CP];   // h @ root2 + b2
// CSR
__device__ int g_cnt   [N_MAX];
__device__ int g_rowoff[N_MAX + 1];
__device__ int g_cur   [N_MAX];
__device__ int g_bsum  [SCAN_BLK];
__device__ __align__(16) int   g_esrc[E_MAX];
__device__ __align__(16) float g_ew  [E_MAX];

// ---------------- CSR build ----------------
__global__ void zero_cnt_kernel(int N) {
    for (int i = blockIdx.x * blockDim.x + threadIdx.x; i < N;
         i += gridDim.x * blockDim.x) g_cnt[i] = 0;
}

__global__ void hist_kernel(const int* __restrict__ ei, int E) {
    int e = blockIdx.x * blockDim.x + threadIdx.x;
    if (e >= E) return;
    atomicAdd(&g_cnt[__ldg(&ei[E + e])], 1);
}

// per-block exclusive scan of g_cnt -> g_rowoff, block totals -> g_bsum
__global__ __launch_bounds__(SCAN_BLK)
void scan1_kernel(int N) {
    __shared__ int s[SCAN_BLK];
    int i = blockIdx.x * SCAN_BLK + threadIdx.x;
    int v = (i < N) ? g_cnt[i] : 0;
    s[threadIdx.x] = v;
    __syncthreads();
#pragma unroll
    for (int off = 1; off < SCAN_BLK; off <<= 1) {
        int add = (threadIdx.x >= off) ? s[threadIdx.x - off] : 0;
        __syncthreads();
        s[threadIdx.x] += add;
        __syncthreads();
    }
    if (i < N) g_rowoff[i] = s[threadIdx.x] - v;          // exclusive within block
    if (threadIdx.x == SCAN_BLK - 1) g_bsum[blockIdx.x] = s[SCAN_BLK - 1];
}

// single-block exclusive scan of block sums (nblk <= 1024)
__global__ __launch_bounds__(SCAN_BLK)
void scan2_kernel(int nblk) {
    __shared__ int s[SCAN_BLK];
    int v = (threadIdx.x < nblk) ? g_bsum[threadIdx.x] : 0;
    s[threadIdx.x] = v;
    __syncthreads();
#pragma unroll
    for (int off = 1; off < SCAN_BLK; off <<= 1) {
        int add = (threadIdx.x >= off) ? s[threadIdx.x - off] : 0;
        __syncthreads();
        s[threadIdx.x] += add;
        __syncthreads();
    }
    if (threadIdx.x < nblk) g_bsum[threadIdx.x] = s[threadIdx.x] - v;
}

__global__ __launch_bounds__(SCAN_BLK)
void scan3_kernel(int N, int E) {
    int i = blockIdx.x * SCAN_BLK + threadIdx.x;
    if (i < N) {
        int v = g_rowoff[i] + g_bsum[blockIdx.x];
        g_rowoff[i] = v;
        g_cur[i]    = v;
    }
    if (i == 0) g_rowoff[N] = E;
}

__global__ void reorder_kernel(const int* __restrict__ ei,
                               const float* __restrict__ attr, int E) {
    int e = blockIdx.x * blockDim.x + threadIdx.x;
    if (e >= E) return;
    int s = __ldg(&ei[e]);
    int d = __ldg(&ei[E + e]);
    int pos = atomicAdd(&g_cur[d], 1);
    g_esrc[pos] = s;
    g_ew[pos]   = __ldg(&attr[e]);
}

// ---------------- layer-1 node transform ----------------
__global__ __launch_bounds__(128)
void node1_kernel(const float* __restrict__ x,
                  const float* __restrict__ W1,
                  const float* __restrict__ root1,
                  const float* __restrict__ b1, int N)
{
    __shared__ float sW0[F_IN * HID];
    __shared__ float sWd[F_IN * HID];
    __shared__ float sR [F_IN * HID];
    for (int i = threadIdx.x; i < F_IN * HID; i += blockDim.x) {
        float w0 = W1[i];
        sW0[i] = w0;
        sWd[i] = W1[F_IN * HID + i] - w0;
        sR [i] = root1[i];
    }
    __syncthreads();

    int n = blockIdx.x * blockDim.x + threadIdx.x;
    if (n >= N) return;

    float acc0[HID], accd[HID], accr[HID];
#pragma unroll
    for (int j = 0; j < HID; j++) { acc0[j] = 0.f; accd[j] = 0.f; accr[j] = 0.f; }

    const float4* xr = reinterpret_cast<const float4*>(x + (size_t)n * F_IN);
#pragma unroll 4
    for (int k4 = 0; k4 < F_IN / 4; k4++) {
        float4 xv = __ldg(&xr[k4]);
        float xs[4] = { xv.x, xv.y, xv.z, xv.w };
#pragma unroll
        for (int kk = 0; kk < 4; kk++) {
            float xk  = xs[kk];
            int  base = (k4 * 4 + kk) * HID;
#pragma unroll
            for (int j4 = 0; j4 < HID / 4; j4++) {
                float4 w0 = *reinterpret_cast<const float4*>(&sW0[base + j4 * 4]);
                float4 wd = *reinterpret_cast<const float4*>(&sWd[base + j4 * 4]);
                float4 wr = *reinterpret_cast<const float4*>(&sR [base + j4 * 4]);
                acc0[j4*4+0] += xk * w0.x; acc0[j4*4+1] += xk * w0.y;
                acc0[j4*4+2] += xk * w0.z; acc0[j4*4+3] += xk * w0.w;
                accd[j4*4+0] += xk * wd.x; accd[j4*4+1] += xk * wd.y;
                accd[j4*4+2] += xk * wd.z; accd[j4*4+3] += xk * wd.w;
                accr[j4*4+0] += xk * wr.x; accr[j4*4+1] += xk * wr.y;
                accr[j4*4+2] += xk * wr.z; accr[j4*4+3] += xk * wr.w;
            }
        }
    }
#pragma unroll
    for (int j4 = 0; j4 < HID / 4; j4++) {
        *reinterpret_cast<float4*>(&g_aq[(size_t)n * 32 + j4 * 4]) =
            make_float4(acc0[j4*4], acc0[j4*4+1], acc0[j4*4+2], acc0[j4*4+3]);
        *reinterpret_cast<float4*>(&g_aq[(size_t)n * 32 + 16 + j4 * 4]) =
            make_float4(accd[j4*4], accd[j4*4+1], accd[j4*4+2], accd[j4*4+3]);
        *reinterpret_cast<float4*>(&g_base1[(size_t)n * HID + j4 * 4]) =
            make_float4(accr[j4*4]   + b1[j4*4],   accr[j4*4+1] + b1[j4*4+1],
                        accr[j4*4+2] + b1[j4*4+2], accr[j4*4+3] + b1[j4*4+3]);
    }
}

// ---------------- layer-1 aggregation: 4 lanes per dst node, atomic-free -----
__global__ void agg1_kernel(int N)
{
    int t = blockIdx.x * blockDim.x + threadIdx.x;
    int n = t >> 2;
    int r = t & 3;
    if (n >= N) return;

    int beg = __ldg(&g_rowoff[n]);
    int end = __ldg(&g_rowoff[n + 1]);

    float4 acc = make_float4(0.f, 0.f, 0.f, 0.f);
    int i = beg;
    for (; i + 2 <= end; i += 2) {
        int   s0 = __ldg(&g_esrc[i]);
        int   s1 = __ldg(&g_esrc[i + 1]);
        float w0 = __ldg(&g_ew[i]);
        float w1 = __ldg(&g_ew[i + 1]);
        float4 a0 = *reinterpret_cast<const float4*>(&g_aq[(size_t)s0 * 32 + r * 4]);
        float4 d0 = *reinterpret_cast<const float4*>(&g_aq[(size_t)s0 * 32 + 16 + r * 4]);
        float4 a1 = *reinterpret_cast<const float4*>(&g_aq[(size_t)s1 * 32 + r * 4]);
        float4 d1 = *reinterpret_cast<const float4*>(&g_aq[(size_t)s1 * 32 + 16 + r * 4]);
        acc.x += a0.x + w0 * d0.x; acc.y += a0.y + w0 * d0.y;
        acc.z += a0.z + w0 * d0.z; acc.w += a0.w + w0 * d0.w;
        acc.x += a1.x + w1 * d1.x; acc.y += a1.y + w1 * d1.y;
        acc.z += a1.z + w1 * d1.z; acc.w += a1.w + w1 * d1.w;
    }
    if (i < end) {
        int   s0 = __ldg(&g_esrc[i]);
        float w0 = __ldg(&g_ew[i]);
        float4 a0 = *reinterpret_cast<const float4*>(&g_aq[(size_t)s0 * 32 + r * 4]);
        float4 d0 = *reinterpret_cast<const float4*>(&g_aq[(size_t)s0 * 32 + 16 + r * 4]);
        acc.x += a0.x + w0 * d0.x; acc.y += a0.y + w0 * d0.y;
        acc.z += a0.z + w0 * d0.z; acc.w += a0.w + w0 * d0.w;
    }

    float inv = 1.f / fmaxf((float)(end - beg), 1.f);
    float4 bs = *reinterpret_cast<const float4*>(&g_base1[(size_t)n * HID + r * 4]);
    float v[4] = { acc.x * inv + bs.x, acc.y * inv + bs.y,
                   acc.z * inv + bs.z, acc.w * inv + bs.w };
    float4 h;
    h.x = (v[0] > 0.f) ? v[0] : expm1f(v[0]);
    h.y = (v[1] > 0.f) ? v[1] : expm1f(v[1]);
    h.z = (v[2] > 0.f) ? v[2] : expm1f(v[2]);
    h.w = (v[3] > 0.f) ? v[3] : expm1f(v[3]);
    *reinterpret_cast<float4*>(&g_h[(size_t)n * HID + r * 4]) = h;
}

// ---------------- layer-2 node transform ----------------
__global__ __launch_bounds__(128)
void node2_kernel(const float* __restrict__ W2,
                  const float* __restrict__ root2,
                  const float* __restrict__ b2, int N)
{
    __shared__ float sB0[HID * CP];
    __shared__ float sBd[HID * CP];
    __shared__ float sR [HID * CP];
    __shared__ float sb2[CP];
    for (int i = threadIdx.x; i < HID * CP; i += blockDim.x) {
        int j = i / CP, c = i - j * CP;
        float w0 = (c < NC) ? W2[j * NC + c] : 0.f;
        float w1 = (c < NC) ? W2[HID * NC + j * NC + c] : 0.f;
        sB0[i] = w0;
        sBd[i] = w1 - w0;
        sR [i] = (c < NC) ? root2[j * NC + c] : 0.f;
    }
    if (threadIdx.x < CP) sb2[threadIdx.x] = (threadIdx.x < NC) ? b2[threadIdx.x] : 0.f;
    __syncthreads();

    int n = blockIdx.x * blockDim.x + threadIdx.x;
    if (n >= N) return;

    float h[HID];
#pragma unroll
    for (int j4 = 0; j4 < HID / 4; j4++) {
        float4 hv = *reinterpret_cast<const float4*>(&g_h[(size_t)n * HID + j4 * 4]);
        h[j4*4+0] = hv.x; h[j4*4+1] = hv.y; h[j4*4+2] = hv.z; h[j4*4+3] = hv.w;
    }

    float o0[CP], od[CP], orr[CP];
#pragma unroll
    for (int c = 0; c < CP; c++) { o0[c] = 0.f; od[c] = 0.f; orr[c] = 0.f; }
#pragma unroll
    for (int j = 0; j < HID; j++) {
        float hj = h[j];
#pragma unroll
        for (int c4 = 0; c4 < CP / 4; c4++) {
            float4 w0 = *reinterpret_cast<const float4*>(&sB0[j * CP + c4 * 4]);
            float4 wd = *reinterpret_cast<const float4*>(&sBd[j * CP + c4 * 4]);
            float4 wr = *reinterpret_cast<const float4*>(&sR [j * CP + c4 * 4]);
            o0[c4*4+0] += hj * w0.x; o0[c4*4+1] += hj * w0.y;
            o0[c4*4+2] += hj * w0.z; o0[c4*4+3] += hj * w0.w;
            od[c4*4+0] += hj * wd.x; od[c4*4+1] += hj * wd.y;
            od[c4*4+2] += hj * wd.z; od[c4*4+3] += hj * wd.w;
            orr[c4*4+0] += hj * wr.x; orr[c4*4+1] += hj * wr.y;
            orr[c4*4+2] += hj * wr.z; orr[c4*4+3] += hj * wr.w;
        }
    }
#pragma unroll
    for (int c4 = 0; c4 < CP / 4; c4++) {
        *reinterpret_cast<float4*>(&g_bq[(size_t)n * 32 + c4 * 4]) =
            make_float4(o0[c4*4], o0[c4*4+1], o0[c4*4+2], o0[c4*4+3]);
        *reinterpret_cast<float4*>(&g_bq[(size_t)n * 32 + 12 + c4 * 4]) =
            make_float4(od[c4*4], od[c4*4+1], od[c4*4+2], od[c4*4+3]);
        *reinterpret_cast<float4*>(&g_base2[(size_t)n * CP + c4 * 4]) =
            make_float4(orr[c4*4]   + sb2[c4*4],   orr[c4*4+1] + sb2[c4*4+1],
                        orr[c4*4+2] + sb2[c4*4+2], orr[c4*4+3] + sb2[c4*4+3]);
    }
}

// ---------------- layer-2 aggregation + output: 3 lanes/node, 10 nodes/warp --
__global__ void agg2_kernel(float* __restrict__ out, int N)
{
    int t    = blockIdx.x * blockDim.x + threadIdx.x;
    int warp = t >> 5;
    int lane = t & 31;
    if (lane >= 30) return;
    int nl = lane / 3;
    int r  = lane - nl * 3;
    int n  = warp * 10 + nl;
    if (n >= N) return;

    int beg = __ldg(&g_rowoff[n]);
    int end = __ldg(&g_rowoff[n + 1]);

    float4 acc = make_float4(0.f, 0.f, 0.f, 0.f);
    int i = beg;
    for (; i + 2 <= end; i += 2) {
        int   s0 = __ldg(&g_esrc[i]);
        int   s1 = __ldg(&g_esrc[i + 1]);
        float w0 = __ldg(&g_ew[i]);
        float w1 = __ldg(&g_ew[i + 1]);
        float4 a0 = *reinterpret_cast<const float4*>(&g_bq[(size_t)s0 * 32 + r * 4]);
        float4 d0 = *reinterpret_cast<const float4*>(&g_bq[(size_t)s0 * 32 + 12 + r * 4]);
        float4 a1 = *reinterpret_cast<const float4*>(&g_bq[(size_t)s1 * 32 + r * 4]);
        float4 d1 = *reinterpret_cast<const float4*>(&g_bq[(size_t)s1 * 32 + 12 + r * 4]);
        acc.x += a0.x + w0 * d0.x; acc.y += a0.y + w0 * d0.y;
        acc.z += a0.z + w0 * d0.z; acc.w += a0.w + w0 * d0.w;
        acc.x += a1.x + w1 * d1.x; acc.y += a1.y + w1 * d1.y;
        acc.z += a1.z + w1 * d1.z; acc.w += a1.w + w1 * d1.w;
    }
    if (i < end) {
        int   s0 = __ldg(&g_esrc[i]);
        float w0 = __ldg(&g_ew[i]);
        float4 a0 = *reinterpret_cast<const float4*>(&g_bq[(size_t)s0 * 32 + r * 4]);
        float4 d0 = *reinterpret_cast<const float4*>(&g_bq[(size_t)s0 * 32 + 12 + r * 4]);
        acc.x += a0.x + w0 * d0.x; acc.y += a0.y + w0 * d0.y;
        acc.z += a0.z + w0 * d0.z; acc.w += a0.w + w0 * d0.w;
    }

    float inv = 1.f / fmaxf((float)(end - beg), 1.f);
    float4 bs = *reinterpret_cast<const float4*>(&g_base2[(size_t)n * CP + r * 4]);
    float o[4] = { acc.x * inv + bs.x, acc.y * inv + bs.y,
                   acc.z * inv + bs.z, acc.w * inv + bs.w };

    float* op = out + (size_t)n * NC + r * 4;
    int lim = NC - r * 4;                 // 4,4,2 for r=0,1,2
#pragma unroll
    for (int q = 0; q < 4; q++)
        if (q < lim) op[q] = o[q];
}

// ---------------- launcher ----------------
extern "C" void kernel_launch(void* const* d_in, const int* in_sizes, int n_in,
                              void* d_out, int out_size)
{
    const float* x     = (const float*)d_in[0];
    const int*   ei    = (const int*)d_in[1];
    const float* attr  = (const float*)d_in[2];
    const float* W1    = (const float*)d_in[3];
    const float* root1 = (const float*)d_in[4];
    const float* b1    = (const float*)d_in[5];
    const float* W2    = (const float*)d_in[6];
    const float* root2 = (const float*)d_in[7];
    const float* b2    = (const float*)d_in[8];
    float*       out   = (float*)d_out;

    int N = in_sizes[0] / F_IN;
    int E = in_sizes[2];
    int nblk = (N + SCAN_BLK - 1) / SCAN_BLK;

    // CSR build (shared by both layers)
    zero_cnt_kernel<<<256, 256>>>(N);
    hist_kernel<<<(E + 255) / 256, 256>>>(ei, E);
    scan1_kernel<<<nblk, SCAN_BLK>>>(N);
    scan2_kernel<<<1, SCAN_BLK>>>(nblk);
    scan3_kernel<<<nblk, SCAN_BLK>>>(N, E);
    reorder_kernel<<<(E + 255) / 256, 256>>>(ei, attr, E);

    // layer 1
    node1_kernel<<<(N + 127) / 128, 128>>>(x, W1, root1, b1, N);
    agg1_kernel<<<(N * 4 + 255) / 256, 256>>>(N);

    // layer 2
    node2_kernel<<<(N + 127) / 128, 128>>>(W2, root2, b2, N);
    long long nwarps = ((long long)N + 9) / 10;
    agg2_kernel<<<(unsigned)((nwarps * 32 + 255) / 256), 256>>>(out, N);
}

// round 7
// speedup vs baseline: 1.1949x; 1.1949x over previous
#include <cuda_runtime.h>
#include <cuda_fp16.h>
#include <stdint.h>
#include <math.h>

#define F_IN 128
#define HID  16
#define NC   10
#define CP   12            // C padded to 12 so scatters are v4-aligned
#define N_MAX 100000
#define E_MAX 1600000

// ---------------- scratch (allocation-free, aligned) ----------------
// fp16 gather tables: one 64B block per node (single cache line per edge gather)
__device__ __align__(16) __half g_aqh [N_MAX * 32];  // a0[16] | ad[16]
__device__ __align__(16) __half g_bqh [N_MAX * 32];  // b0[12] pad[4] | bd[12] pad[4]
// fp32 accumulators / bases
__device__ __align__(16) float g_base1[N_MAX * HID];  // x @ root1 + b1
__device__ __align__(16) float g_agg1 [N_MAX * HID];
__device__ __align__(16) float g_deg  [N_MAX];
__device__ __align__(16) float g_base2[N_MAX * CP];   // h @ root2 + b2
__device__ __align__(16) float g_agg2 [N_MAX * CP];

static __device__ __forceinline__ unsigned int pack_h2(float a, float b) {
    __half2 h = __floats2half2_rn(a, b);
    return *reinterpret_cast<unsigned int*>(&h);
}

// ---------------- zero accumulators ----------------
__global__ void zero_kernel(int N) {
    int total = N * HID + N * CP + N;     // agg1 + agg2 + deg
    for (int i = blockIdx.x * blockDim.x + threadIdx.x; i < total;
         i += gridDim.x * blockDim.x) {
        if (i < N * HID)               g_agg1[i] = 0.f;
        else if (i < N * HID + N * CP) g_agg2[i - N * HID] = 0.f;
        else                           g_deg[i - N * HID - N * CP] = 0.f;
    }
}

// ---------------- layer-1 node transform ----------------
// per node: a0 = x@W0, ad = x@(W1-W0)  -> fp16 interleaved; base1 = x@root1+b1
__global__ __launch_bounds__(128)
void node1_kernel(const float* __restrict__ x,
                  const float* __restrict__ W1,
                  const float* __restrict__ root1,
                  const float* __restrict__ b1, int N)
{
    __shared__ float sW0[F_IN * HID];
    __shared__ float sWd[F_IN * HID];
    __shared__ float sR [F_IN * HID];
    for (int i = threadIdx.x; i < F_IN * HID; i += blockDim.x) {
        float w0 = W1[i];
        sW0[i] = w0;
        sWd[i] = W1[F_IN * HID + i] - w0;
        sR [i] = root1[i];
    }
    __syncthreads();

    int n = blockIdx.x * blockDim.x + threadIdx.x;
    if (n >= N) return;

    float acc0[HID], accd[HID], accr[HID];
#pragma unroll
    for (int j = 0; j < HID; j++) { acc0[j] = 0.f; accd[j] = 0.f; accr[j] = 0.f; }

    const float4* xr = reinterpret_cast<const float4*>(x + (size_t)n * F_IN);
#pragma unroll 4
    for (int k4 = 0; k4 < F_IN / 4; k4++) {
        float4 xv = __ldg(&xr[k4]);
        float xs[4] = { xv.x, xv.y, xv.z, xv.w };
#pragma unroll
        for (int kk = 0; kk < 4; kk++) {
            float xk  = xs[kk];
            int  base = (k4 * 4 + kk) * HID;
#pragma unroll
            for (int j4 = 0; j4 < HID / 4; j4++) {
                float4 w0 = *reinterpret_cast<const float4*>(&sW0[base + j4 * 4]);
                float4 wd = *reinterpret_cast<const float4*>(&sWd[base + j4 * 4]);
                float4 wr = *reinterpret_cast<const float4*>(&sR [base + j4 * 4]);
                acc0[j4*4+0] += xk * w0.x; acc0[j4*4+1] += xk * w0.y;
                acc0[j4*4+2] += xk * w0.z; acc0[j4*4+3] += xk * w0.w;
                accd[j4*4+0] += xk * wd.x; accd[j4*4+1] += xk * wd.y;
                accd[j4*4+2] += xk * wd.z; accd[j4*4+3] += xk * wd.w;
                accr[j4*4+0] += xk * wr.x; accr[j4*4+1] += xk * wr.y;
                accr[j4*4+2] += xk * wr.z; accr[j4*4+3] += xk * wr.w;
            }
        }
    }
    // pack a0|ad as halves: 16 halves each = 32B + 32B, one 64B block
    uint4 pa, pa2, pd, pd2;
    pa.x  = pack_h2(acc0[0],  acc0[1]);  pa.y  = pack_h2(acc0[2],  acc0[3]);
    pa.z  = pack_h2(acc0[4],  acc0[5]);  pa.w  = pack_h2(acc0[6],  acc0[7]);
    pa2.x = pack_h2(acc0[8],  acc0[9]);  pa2.y = pack_h2(acc0[10], acc0[11]);
    pa2.z = pack_h2(acc0[12], acc0[13]); pa2.w = pack_h2(acc0[14], acc0[15]);
    pd.x  = pack_h2(accd[0],  accd[1]);  pd.y  = pack_h2(accd[2],  accd[3]);
    pd.z  = pack_h2(accd[4],  accd[5]);  pd.w  = pack_h2(accd[6],  accd[7]);
    pd2.x = pack_h2(accd[8],  accd[9]);  pd2.y = pack_h2(accd[10], accd[11]);
    pd2.z = pack_h2(accd[12], accd[13]); pd2.w = pack_h2(accd[14], accd[15]);

    uint4* dst = reinterpret_cast<uint4*>(&g_aqh[(size_t)n * 32]);
    dst[0] = pa;  dst[1] = pa2;  dst[2] = pd;  dst[3] = pd2;

#pragma unroll
    for (int j4 = 0; j4 < HID / 4; j4++) {
        *reinterpret_cast<float4*>(&g_base1[(size_t)n * HID + j4 * 4]) =
            make_float4(accr[j4*4]   + b1[j4*4],   accr[j4*4+1] + b1[j4*4+1],
                        accr[j4*4+2] + b1[j4*4+2], accr[j4*4+3] + b1[j4*4+3]);
    }
}

// ---------------- layer-1 edge pass: 4 lanes per edge, fp16 gather -----------
__global__ void edge1_kernel(const int* __restrict__ ei,
                             const float* __restrict__ attr, int E)
{
    int t = blockIdx.x * blockDim.x + threadIdx.x;
    int e = t >> 2;
    int r = t & 3;
    if (e >= E) return;
    int   s = __ldg(&ei[e]);
    int   d = __ldg(&ei[E + e]);
    float w = __ldg(&attr[e]);

    // lane r: a0 halves [r*4 .. r*4+3], ad halves [16+r*4 ..]
    const uint2* pa = reinterpret_cast<const uint2*>(&g_aqh[(size_t)s * 32 + r * 4]);
    const uint2* pd = reinterpret_cast<const uint2*>(&g_aqh[(size_t)s * 32 + 16 + r * 4]);
    uint2 ua = __ldg(pa);
    uint2 ud = __ldg(pd);
    float2 a01 = __half22float2(*reinterpret_cast<__half2*>(&ua.x));
    float2 a23 = __half22float2(*reinterpret_cast<__half2*>(&ua.y));
    float2 d01 = __half22float2(*reinterpret_cast<__half2*>(&ud.x));
    float2 d23 = __half22float2(*reinterpret_cast<__half2*>(&ud.y));

    float4 msg = make_float4(fmaf(w, d01.x, a01.x), fmaf(w, d01.y, a01.y),
                             fmaf(w, d23.x, a23.x), fmaf(w, d23.y, a23.y));
    float* dstp = &g_agg1[(size_t)d * HID + r * 4];
    asm volatile("red.global.add.v4.f32 [%0], {%1,%2,%3,%4};"
                 :: "l"(dstp), "f"(msg.x), "f"(msg.y), "f"(msg.z), "f"(msg.w)
                 : "memory");
    if (r == 0) atomicAdd(&g_deg[d], 1.0f);
}

// ---------------- layer-1 finalize + ELU + layer-2 node transform ------------
__global__ __launch_bounds__(128)
void node2_kernel(const float* __restrict__ W2,
                  const float* __restrict__ root2,
                  const float* __restrict__ b2, int N)
{
    __shared__ float sB0[HID * CP];
    __shared__ float sBd[HID * CP];
    __shared__ float sR [HID * CP];
    __shared__ float sb2[CP];
    for (int i = threadIdx.x; i < HID * CP; i += blockDim.x) {
        int j = i / CP, c = i - j * CP;
        float w0 = (c < NC) ? W2[j * NC + c] : 0.f;
        float w1 = (c < NC) ? W2[HID * NC + j * NC + c] : 0.f;
        sB0[i] = w0;
        sBd[i] = w1 - w0;
        sR [i] = (c < NC) ? root2[j * NC + c] : 0.f;
    }
    if (threadIdx.x < CP) sb2[threadIdx.x] = (threadIdx.x < NC) ? b2[threadIdx.x] : 0.f;
    __syncthreads();

    int n = blockIdx.x * blockDim.x + threadIdx.x;
    if (n >= N) return;

    float inv = 1.f / fmaxf(g_deg[n], 1.f);
    float h[HID];
#pragma unroll
    for (int j4 = 0; j4 < HID / 4; j4++) {
        float4 ag = *reinterpret_cast<const float4*>(&g_agg1 [(size_t)n * HID + j4 * 4]);
        float4 bs = *reinterpret_cast<const float4*>(&g_base1[(size_t)n * HID + j4 * 4]);
        float v[4] = { ag.x * inv + bs.x, ag.y * inv + bs.y,
                       ag.z * inv + bs.z, ag.w * inv + bs.w };
#pragma unroll
        for (int q = 0; q < 4; q++)
            h[j4 * 4 + q] = (v[q] > 0.f) ? v[q] : expm1f(v[q]);
    }

    float o0[CP], od[CP], orr[CP];
#pragma unroll
    for (int c = 0; c < CP; c++) { o0[c] = 0.f; od[c] = 0.f; orr[c] = 0.f; }
#pragma unroll
    for (int j = 0; j < HID; j++) {
        float hj = h[j];
#pragma unroll
        for (int c4 = 0; c4 < CP / 4; c4++) {
            float4 w0 = *reinterpret_cast<const float4*>(&sB0[j * CP + c4 * 4]);
            float4 wd = *reinterpret_cast<const float4*>(&sBd[j * CP + c4 * 4]);
            float4 wr = *reinterpret_cast<const float4*>(&sR [j * CP + c4 * 4]);
            o0[c4*4+0] += hj * w0.x; o0[c4*4+1] += hj * w0.y;
            o0[c4*4+2] += hj * w0.z; o0[c4*4+3] += hj * w0.w;
            od[c4*4+0] += hj * wd.x; od[c4*4+1] += hj * wd.y;
            od[c4*4+2] += hj * wd.z; od[c4*4+3] += hj * wd.w;
            orr[c4*4+0] += hj * wr.x; orr[c4*4+1] += hj * wr.y;
            orr[c4*4+2] += hj * wr.z; orr[c4*4+3] += hj * wr.w;
        }
    }
    // pack b0 (12) and bd (12) halves into 64B node block: b0 @0, bd @16
    uint4 q0, q2;
    uint2 q1, q3;
    q0.x = pack_h2(o0[0],  o0[1]);  q0.y = pack_h2(o0[2],  o0[3]);
    q0.z = pack_h2(o0[4],  o0[5]);  q0.w = pack_h2(o0[6],  o0[7]);
    q1.x = pack_h2(o0[8],  o0[9]);  q1.y = pack_h2(o0[10], o0[11]);
    q2.x = pack_h2(od[0],  od[1]);  q2.y = pack_h2(od[2],  od[3]);
    q2.z = pack_h2(od[4],  od[5]);  q2.w = pack_h2(od[6],  od[7]);
    q3.x = pack_h2(od[8],  od[9]);  q3.y = pack_h2(od[10], od[11]);

    __half* blk = &g_bqh[(size_t)n * 32];
    *reinterpret_cast<uint4*>(blk)      = q0;
    *reinterpret_cast<uint2*>(blk + 8)  = q1;   // halves 8..11 (pad 12..15 unused)
    *reinterpret_cast<uint4*>(blk + 16) = q2;
    *reinterpret_cast<uint2*>(blk + 24) = q3;

#pragma unroll
    for (int c4 = 0; c4 < CP / 4; c4++) {
        *reinterpret_cast<float4*>(&g_base2[(size_t)n * CP + c4 * 4]) =
            make_float4(orr[c4*4]   + sb2[c4*4],   orr[c4*4+1] + sb2[c4*4+1],
                        orr[c4*4+2] + sb2[c4*4+2], orr[c4*4+3] + sb2[c4*4+3]);
    }
}

// ---------------- layer-2 edge pass: 3 lanes/edge, 10 edges/warp, fp16 gather
__global__ void edge2_kernel(const int* __restrict__ ei,
                             const float* __restrict__ attr, int E)
{
    int t    = blockIdx.x * blockDim.x + threadIdx.x;
    int warp = t >> 5;
    int lane = t & 31;
    if (lane >= 30) return;
    int el = lane / 3;                // 0..9
    int r  = lane - el * 3;           // 0..2
    int e  = warp * 10 + el;
    if (e >= E) return;

    int   s = __ldg(&ei[e]);
    int   d = __ldg(&ei[E + e]);
    float w = __ldg(&attr[e]);

    const uint2* pb = reinterpret_cast<const uint2*>(&g_bqh[(size_t)s * 32 + r * 4]);
    const uint2* pq = reinterpret_cast<const uint2*>(&g_bqh[(size_t)s * 32 + 16 + r * 4]);
    uint2 ub = __ldg(pb);
    uint2 ud = __ldg(pq);
    float2 b01 = __half22float2(*reinterpret_cast<__half2*>(&ub.x));
    float2 b23 = __half22float2(*reinterpret_cast<__half2*>(&ub.y));
    float2 d01 = __half22float2(*reinterpret_cast<__half2*>(&ud.x));
    float2 d23 = __half22float2(*reinterpret_cast<__half2*>(&ud.y));

    float4 msg = make_float4(fmaf(w, d01.x, b01.x), fmaf(w, d01.y, b01.y),
                             fmaf(w, d23.x, b23.x), fmaf(w, d23.y, b23.y));
    float* dstp = &g_agg2[(size_t)d * CP + r * 4];
    asm volatile("red.global.add.v4.f32 [%0], {%1,%2,%3,%4};"
                 :: "l"(dstp), "f"(msg.x), "f"(msg.y), "f"(msg.z), "f"(msg.w)
                 : "memory");
}

// ---------------- output ----------------
__global__ void out_kernel(float* __restrict__ out, int N)
{
    int t = blockIdx.x * blockDim.x + threadIdx.x;
    if (t >= N * NC) return;
    int n = t / NC;
    int c = t - n * NC;
    float inv = 1.f / fmaxf(g_deg[n], 1.f);
    out[t] = g_agg2[(size_t)n * CP + c] * inv + g_base2[(size_t)n * CP + c];
}

// ---------------- launcher ----------------
extern "C" void kernel_launch(void* const* d_in, const int* in_sizes, int n_in,
                              void* d_out, int out_size)
{
    const float* x     = (const float*)d_in[0];
    const int*   ei    = (const int*)d_in[1];     // int64 in ref -> int32 on device
    const float* attr  = (const float*)d_in[2];
    const float* W1    = (const float*)d_in[3];
    const float* root1 = (const float*)d_in[4];
    const float* b1    = (const float*)d_in[5];
    const float* W2    = (const float*)d_in[6];
    const float* root2 = (const float*)d_in[7];
    const float* b2    = (const float*)d_in[8];
    float*       out   = (float*)d_out;

    int N = in_sizes[0] / F_IN;
    int E = in_sizes[2];           // edge_attr is (E,1)

    zero_kernel<<<1024, 256>>>(N);
    node1_kernel<<<(N + 127) / 128, 128>>>(x, W1, root1, b1, N);

    long long t1 = (long long)E * 4;
    edge1_kernel<<<(unsigned)((t1 + 255) / 256), 256>>>(ei, attr, E);

    node2_kernel<<<(N + 127) / 128, 128>>>(W2, root2, b2, N);

    long long nwarps = ((long long)E + 9) / 10;
    long long t2 = nwarps * 32;
    edge2_kernel<<<(unsigned)((t2 + 255) / 256), 256>>>(ei, attr, E);

    out_kernel<<<(N * NC + 255) / 256, 256>>>(out, N);
}